// round 2
// baseline (speedup 1.0000x reference)
#include <cuda_runtime.h>

// Problem constants
#define G_     2
#define BATCH_ 128
#define L_     2048
#define SD_    64
#define ID_    16
#define OD_    16
#define C_     16            // chunks per sequence
#define T_     (L_/C_)       // 128 steps per chunk

// ---------- device scratch (no allocations allowed) ----------
__device__ float g_FT[G_*SD_*SD_];              // F^T per group
__device__ float g_carry[G_*BATCH_*C_*SD_];     // incoming true state per chunk

// ---------- f32x2 packed helpers ----------
__device__ __forceinline__ unsigned long long pack2(float lo, float hi) {
    unsigned long long r;
    asm("mov.b64 %0, {%1, %2};" : "=l"(r) : "f"(lo), "f"(hi));
    return r;
}
__device__ __forceinline__ void unpack2(unsigned long long v, float& lo, float& hi) {
    asm("mov.b64 {%0, %1}, %2;" : "=f"(lo), "=f"(hi) : "l"(v));
}
__device__ __forceinline__ void fma2(unsigned long long& acc, unsigned long long a, unsigned long long b) {
    asm("fma.rn.f32x2 %0, %1, %2, %0;" : "+l"(acc) : "l"(a), "l"(b));
}

// ============================================================================
// K0: FT = F^(T_) via 7 repeated squarings (T_ = 128 = 2^7). grid = G_, 512 thr
// ============================================================================
__global__ void __launch_bounds__(512) power_kernel(const float* __restrict__ Fm) {
    __shared__ float A[SD_*SD_];
    __shared__ float Bb[SD_*SD_];
    const int g = blockIdx.x, tid = threadIdx.x;
    for (int i = tid; i < SD_*SD_; i += 512) A[i] = Fm[g*SD_*SD_ + i];
    __syncthreads();
    const int r  = tid >> 3;
    const int cq = (tid & 7) * 8;
    for (int it = 0; it < 7; it++) {
        const float* src = (it & 1) ? Bb : A;
        float*       dst = (it & 1) ? A  : Bb;
        float acc[8];
        #pragma unroll
        for (int j = 0; j < 8; j++) acc[j] = 0.f;
        for (int k = 0; k < SD_; k++) {
            float a = src[r*SD_ + k];
            #pragma unroll
            for (int j = 0; j < 8; j++) acc[j] += a * src[k*SD_ + cq + j];
        }
        __syncthreads();
        #pragma unroll
        for (int j = 0; j < 8; j++) dst[r*SD_ + cq + j] = acc[j];
        __syncthreads();
    }
    // after 7 iterations result is in Bb
    for (int i = tid; i < SD_*SD_; i += 512) g_FT[g*SD_*SD_ + i] = Bb[i];
}

// ============================================================================
// K1: chunk-local scans. grid = G_*BATCH_*C_, block = 64.
// Writes local states + local obs (H*s_local + SV*v). Chunk 0 is exact.
// ============================================================================
__global__ void __launch_bounds__(64)
scan_kernel(const float* __restrict__ state,
            const float* __restrict__ inputs,
            const float* __restrict__ Fm,
            const float* __restrict__ Bm,
            const float* __restrict__ Hm,
            const float* __restrict__ SW,
            const float* __restrict__ SV,
            const float* __restrict__ wn,
            const float* __restrict__ vnz,
            float* __restrict__ states_out,
            float* __restrict__ obs_out)
{
    const int t  = threadIdx.x;                    // 0..63
    const int c  = (int)(blockIdx.x % C_);
    const int gb = (int)(blockIdx.x / C_);
    const int g  = gb / BATCH_;
    const int b  = gb % BATCH_;
    const int l0 = c * T_;                         // even

    __shared__ __align__(16) float s_sh[2][SD_];
    __shared__ __align__(16) float w_sh[2][SD_];
    __shared__ __align__(16) float in_sh[2][ID_];
    __shared__ __align__(16) float vn_sh[2][OD_];
    __shared__ __align__(16) float part_sh[2][SD_];

    // per-thread matrix rows in registers (f32x2 packed)
    unsigned long long f2v[SD_/2], sw2[SD_/2], b2v[ID_/2], h2v[8], sv2[OD_/2];
    {
        const float* Frow  = Fm + ((size_t)g*SD_ + t)*SD_;
        const float* SWrow = SW + ((size_t)g*SD_ + t)*SD_;
        #pragma unroll
        for (int i = 0; i < SD_/2; i++) {
            f2v[i] = pack2(Frow[2*i],  Frow[2*i+1]);
            sw2[i] = pack2(SWrow[2*i], SWrow[2*i+1]);
        }
        const float* Brow = Bm + ((size_t)g*SD_ + t)*ID_;
        #pragma unroll
        for (int i = 0; i < ID_/2; i++) b2v[i] = pack2(Brow[2*i], Brow[2*i+1]);

        const int p = t & 15, q = t >> 4;
        const float* Hrow = Hm + ((size_t)g*OD_ + p)*SD_ + q*16;
        #pragma unroll
        for (int i = 0; i < 8; i++) h2v[i] = pack2(Hrow[2*i], Hrow[2*i+1]);

        if (t < OD_) {
            const float* SVrow = SV + ((size_t)g*OD_ + t)*OD_;
            #pragma unroll
            for (int i = 0; i < OD_/2; i++) sv2[i] = pack2(SVrow[2*i], SVrow[2*i+1]);
        }
    }

    // initial local state: real state for chunk 0, zero otherwise
    s_sh[0][t] = (c == 0) ? state[(size_t)gb*SD_ + t] : 0.f;

    const float* w_base  = wn  + ((size_t)g*BATCH_ + b)*SD_;
    const float* in_base = inputs + (size_t)gb*L_*ID_;
    const float* vn_base = vnz + ((size_t)g*BATCH_ + b)*OD_;
    const long wstep = (long)G_*BATCH_*SD_;
    const long vstep = (long)G_*BATCH_*OD_;

    // prefetch ring depth 4
    float w_pf[4], in_pf[4], vn_pf[4];
    #pragma unroll
    for (int j = 0; j < 4; j++) {
        w_pf[j] = w_base[(long)(l0+j)*wstep + t];
        if (t < ID_) in_pf[j] = in_base[(long)(l0+j)*ID_ + t];
        if (t < OD_) vn_pf[j] = vn_base[(long)(l0+j)*vstep + t];
    }

    float* st_out = states_out + (size_t)gb*L_*SD_;
    float* ob_out = obs_out    + (size_t)gb*L_*OD_;

    for (int l4 = l0; l4 < l0 + T_; l4 += 4) {
        #pragma unroll
        for (int j = 0; j < 4; j++) {
            const int l  = l4 + j;
            const int pb = l & 1;

            w_sh[pb][t] = w_pf[j];
            if (t < ID_) in_sh[pb][t] = in_pf[j];
            if (t < OD_) vn_sh[pb][t] = vn_pf[j];

            const int lp = l + 4;
            if (lp < l0 + T_) {
                w_pf[j] = w_base[(long)lp*wstep + t];
                if (t < ID_) in_pf[j] = in_base[(long)lp*ID_ + t];
                if (t < OD_) vn_pf[j] = vn_base[(long)lp*vstep + t];
            }

            __syncthreads();   // staged data + part_sh[pb^1] + s_sh[pb] visible

            // finalize local obs for step l-1 (within this chunk only)
            if (l > l0 && t < OD_) {
                const int fb = pb ^ 1;
                float o = (part_sh[fb][t]    + part_sh[fb][t+16])
                        + (part_sh[fb][t+32] + part_sh[fb][t+48]);
                unsigned long long oacc = 0ULL;
                const ulonglong2* vnp = (const ulonglong2*)vn_sh[fb];
                #pragma unroll
                for (int i = 0; i < 4; i++) {
                    ulonglong2 v = vnp[i];
                    fma2(oacc, sv2[2*i],   v.x);
                    fma2(oacc, sv2[2*i+1], v.y);
                }
                float a0, a1; unpack2(oacc, a0, a1);
                ob_out[(long)(l-1)*OD_ + t] = o + a0 + a1;
            }

            // s_l = F*s_{l-1} + SW*w_l + B*u_l
            unsigned long long acc0 = 0ULL, acc1 = 0ULL, acc2 = 0ULL, acc3 = 0ULL;
            const ulonglong2* sp = (const ulonglong2*)s_sh[pb];
            const ulonglong2* wp = (const ulonglong2*)w_sh[pb];
            const ulonglong2* ip = (const ulonglong2*)in_sh[pb];
            #pragma unroll
            for (int i = 0; i < 16; i += 2) {
                ulonglong2 va = sp[i], vb = sp[i+1];
                fma2(acc0, f2v[2*i],   va.x);
                fma2(acc1, f2v[2*i+1], va.y);
                fma2(acc2, f2v[2*i+2], vb.x);
                fma2(acc3, f2v[2*i+3], vb.y);
            }
            #pragma unroll
            for (int i = 0; i < 16; i += 2) {
                ulonglong2 va = wp[i], vb = wp[i+1];
                fma2(acc0, sw2[2*i],   va.x);
                fma2(acc1, sw2[2*i+1], va.y);
                fma2(acc2, sw2[2*i+2], vb.x);
                fma2(acc3, sw2[2*i+3], vb.y);
            }
            #pragma unroll
            for (int i = 0; i < 4; i += 2) {
                ulonglong2 va = ip[i], vb = ip[i+1];
                fma2(acc0, b2v[2*i],   va.x);
                fma2(acc1, b2v[2*i+1], va.y);
                fma2(acc2, b2v[2*i+2], vb.x);
                fma2(acc3, b2v[2*i+3], vb.y);
            }
            float x0,x1,y0,y1,z0,z1,u0,u1;
            unpack2(acc0,x0,x1); unpack2(acc1,y0,y1);
            unpack2(acc2,z0,z1); unpack2(acc3,u0,u1);
            const float sval = ((x0+x1)+(y0+y1)) + ((z0+z1)+(u0+u1));

            s_sh[pb^1][t] = sval;
            st_out[(long)l*SD_ + t] = sval;

            __syncthreads();   // s_l complete

            // H partial on s_l
            {
                const int q = t >> 4;
                unsigned long long pacc = 0ULL;
                const ulonglong2* snp = (const ulonglong2*)(s_sh[pb^1] + q*16);
                #pragma unroll
                for (int i = 0; i < 4; i++) {
                    ulonglong2 v = snp[i];
                    fma2(pacc, h2v[2*i],   v.x);
                    fma2(pacc, h2v[2*i+1], v.y);
                }
                float a0, a1; unpack2(pacc, a0, a1);
                part_sh[pb][t] = a0 + a1;
            }
        }
    }

    // epilogue: local obs for last step of chunk
    __syncthreads();
    if (t < OD_) {
        const int fb = (l0 + T_ - 1) & 1;   // = 1
        float o = (part_sh[fb][t]    + part_sh[fb][t+16])
                + (part_sh[fb][t+32] + part_sh[fb][t+48]);
        unsigned long long oacc = 0ULL;
        const ulonglong2* vnp = (const ulonglong2*)vn_sh[fb];
        #pragma unroll
        for (int i = 0; i < 4; i++) {
            ulonglong2 v = vnp[i];
            fma2(oacc, sv2[2*i],   v.x);
            fma2(oacc, sv2[2*i+1], v.y);
        }
        float a0, a1; unpack2(oacc, a0, a1);
        ob_out[(long)(l0 + T_ - 1)*OD_ + t] = o + a0 + a1;
    }
}

// ============================================================================
// K2: carry propagation across chunks. grid = G_*BATCH_, block = 64.
// true_end[c] = local_end[c] + FT * true_end[c-1]; carry[c] = true_end[c-1].
// ============================================================================
__global__ void __launch_bounds__(64) carry_kernel(const float* __restrict__ states_out) {
    const int t = threadIdx.x, gb = blockIdx.x, g = gb / BATCH_;
    __shared__ float te_sh[SD_];

    float ft[SD_];
    #pragma unroll
    for (int i = 0; i < SD_; i++) ft[i] = g_FT[((size_t)g*SD_ + t)*SD_ + i];

    float te = states_out[((size_t)gb*L_ + T_ - 1)*SD_ + t];   // true end of chunk 0
    for (int c = 1; c < C_; c++) {
        g_carry[((size_t)gb*C_ + c)*SD_ + t] = te;
        __syncthreads();
        te_sh[t] = te;
        __syncthreads();
        float acc = 0.f;
        #pragma unroll
        for (int i = 0; i < SD_; i++) acc += ft[i] * te_sh[i];
        te = states_out[((size_t)gb*L_ + (size_t)(c+1)*T_ - 1)*SD_ + t] + acc;
    }
}

// ============================================================================
// K3: fixup. grid = G_*BATCH_*(C_-1), block = 64.
// q_{k+1} = F q_k (q_0 = carry); states[l0+k] += q_{k+1}; obs[l0+k] += H q_{k+1}
// ============================================================================
__global__ void __launch_bounds__(64)
fixup_kernel(const float* __restrict__ Fm,
             const float* __restrict__ Hm,
             float* __restrict__ states_out,
             float* __restrict__ obs_out)
{
    const int t  = threadIdx.x;
    const int nb = C_ - 1;
    const int c  = 1 + (int)(blockIdx.x % nb);
    const int gb = (int)(blockIdx.x / nb);
    const int g  = gb / BATCH_;
    const int l0 = c * T_;

    __shared__ __align__(16) float q_sh[2][SD_];
    __shared__ __align__(16) float part_sh[2][SD_];

    unsigned long long f2v[SD_/2], h2v[8];
    {
        const float* Frow = Fm + ((size_t)g*SD_ + t)*SD_;
        #pragma unroll
        for (int i = 0; i < SD_/2; i++) f2v[i] = pack2(Frow[2*i], Frow[2*i+1]);
        const int p = t & 15, qq = t >> 4;
        const float* Hrow = Hm + ((size_t)g*OD_ + p)*SD_ + qq*16;
        #pragma unroll
        for (int i = 0; i < 8; i++) h2v[i] = pack2(Hrow[2*i], Hrow[2*i+1]);
    }

    q_sh[0][t] = g_carry[((size_t)gb*C_ + c)*SD_ + t];

    float* st = states_out + ((size_t)gb*L_ + l0)*SD_;
    float* ob = obs_out    + ((size_t)gb*L_ + l0)*OD_;

    float st_pf[4], ob_pf[4];
    #pragma unroll
    for (int j = 0; j < 4; j++) {
        st_pf[j] = st[(long)j*SD_ + t];
        if (t < OD_) ob_pf[j] = ob[(long)j*OD_ + t];
    }
    float ob_prev = 0.f;

    for (int k4 = 0; k4 < T_; k4 += 4) {
        #pragma unroll
        for (int j = 0; j < 4; j++) {
            const int k  = k4 + j;
            const int pb = k & 1;
            const float st_cur = st_pf[j];
            const float ob_cur = (t < OD_) ? ob_pf[j] : 0.f;
            const int kp = k + 4;
            if (kp < T_) {
                st_pf[j] = st[(long)kp*SD_ + t];
                if (t < OD_) ob_pf[j] = ob[(long)kp*OD_ + t];
            }

            __syncthreads();   // q_sh[pb] ready; part_sh[pb^1] ready

            if (k > 0 && t < OD_) {
                const int fb = pb ^ 1;
                float o = (part_sh[fb][t]    + part_sh[fb][t+16])
                        + (part_sh[fb][t+32] + part_sh[fb][t+48]);
                ob[(long)(k-1)*OD_ + t] = ob_prev + o;
            }

            // q_{k+1} = F * q_k
            unsigned long long a0=0ULL, a1=0ULL, a2=0ULL, a3=0ULL;
            const ulonglong2* qp = (const ulonglong2*)q_sh[pb];
            #pragma unroll
            for (int i = 0; i < 16; i += 2) {
                ulonglong2 va = qp[i], vb = qp[i+1];
                fma2(a0, f2v[2*i],   va.x);
                fma2(a1, f2v[2*i+1], va.y);
                fma2(a2, f2v[2*i+2], vb.x);
                fma2(a3, f2v[2*i+3], vb.y);
            }
            float x0,x1,y0,y1,z0,z1,u0,u1;
            unpack2(a0,x0,x1); unpack2(a1,y0,y1); unpack2(a2,z0,z1); unpack2(a3,u0,u1);
            const float qn = ((x0+x1)+(y0+y1)) + ((z0+z1)+(u0+u1));

            st[(long)k*SD_ + t] = st_cur + qn;
            q_sh[pb^1][t] = qn;

            __syncthreads();   // q_{k+1} visible

            {
                const int qq = t >> 4;
                unsigned long long pa = 0ULL;
                const ulonglong2* qnp = (const ulonglong2*)(q_sh[pb^1] + qq*16);
                #pragma unroll
                for (int i = 0; i < 4; i++) {
                    ulonglong2 v = qnp[i];
                    fma2(pa, h2v[2*i],   v.x);
                    fma2(pa, h2v[2*i+1], v.y);
                }
                float a, b2; unpack2(pa, a, b2);
                part_sh[pb][t] = a + b2;
            }
            ob_prev = ob_cur;
        }
    }
    __syncthreads();
    if (t < OD_) {
        const int fb = (T_ - 1) & 1;   // = 1
        float o = (part_sh[fb][t]    + part_sh[fb][t+16])
                + (part_sh[fb][t+32] + part_sh[fb][t+48]);
        ob[(long)(T_-1)*OD_ + t] = ob_prev + o;
    }
}

// ============================================================================
extern "C" void kernel_launch(void* const* d_in, const int* in_sizes, int n_in,
                              void* d_out, int out_size) {
    const float* state  = (const float*)d_in[0];   // [G,B,S]
    const float* inputs = (const float*)d_in[1];   // [G,B,L,I]
    const float* Fm     = (const float*)d_in[2];   // [G,S,S]
    const float* Bm     = (const float*)d_in[3];   // [G,S,I]
    const float* Hm     = (const float*)d_in[4];   // [G,O,S]
    const float* SW     = (const float*)d_in[5];   // [G,S,S]
    const float* SV     = (const float*)d_in[6];   // [G,O,O]
    const float* wn     = (const float*)d_in[7];   // [L,G,B,S]
    const float* vn     = (const float*)d_in[8];   // [L,G,B,O]

    float* states_out = (float*)d_out;                           // [G,B,L,S]
    float* obs_out    = states_out + (size_t)G_*BATCH_*L_*SD_;   // [G,B,L,O]

    power_kernel<<<G_, 512>>>(Fm);
    scan_kernel<<<G_*BATCH_*C_, 64>>>(state, inputs, Fm, Bm, Hm, SW, SV,
                                      wn, vn, states_out, obs_out);
    carry_kernel<<<G_*BATCH_, 64>>>(states_out);
    fixup_kernel<<<G_*BATCH_*(C_-1), 64>>>(Fm, Hm, states_out, obs_out);
}